// round 1
// baseline (speedup 1.0000x reference)
#include <cuda_runtime.h>
#include <cstdint>

#define Nn 100000
#define Hh 64
#define Ee 1000000
#define Rr 3

// ---------------- scratch (device globals, no allocation) ----------------
__device__ float g_h   [Nn * Hh];
__device__ float g_h0  [Nn * Hh];
__device__ float g_h1  [Nn * Hh];
__device__ float g_hall[Nn * Hh];
__device__ float g_scal[Nn * Hh];
__device__ float g_acc [Nn * Hh];
__device__ float g_dinv[Rr * Nn];

// ---------------- f32x2 helpers (Blackwell packed fp32) ----------------
__device__ __forceinline__ unsigned long long pk2(float lo, float hi) {
    unsigned long long r;
    asm("mov.b64 %0,{%1,%2};" : "=l"(r) : "f"(lo), "f"(hi));
    return r;
}
__device__ __forceinline__ void fma2(unsigned long long& d, unsigned long long a, unsigned long long b) {
    asm("fma.rn.f32x2 %0,%1,%2,%0;" : "+l"(d) : "l"(a), "l"(b));
}
__device__ __forceinline__ float2 upk2(unsigned long long v) {
    float2 f;
    asm("mov.b64 {%0,%1},%2;" : "=f"(f.x), "=f"(f.y) : "l"(v));
    return f;
}

// ---------------- degree / dinv ----------------
__global__ void zero_dinv_kernel(float* deg) {
    int i = blockIdx.x * 256 + threadIdx.x;
    if (i < Rr * Nn) deg[i] = 0.f;
}
__global__ void count_deg_kernel(const int* __restrict__ dst, float* deg) {
    int i = blockIdx.x * 256 + threadIdx.x;
    if (i < Rr * Ee) {
        int r = i / Ee;
        atomicAdd(&deg[r * Nn + dst[i]], 1.0f);
    }
}
__global__ void fin_dinv_kernel(float* deg) {
    int i = blockIdx.x * 256 + threadIdx.x;
    if (i < Rr * Nn) deg[i] = rsqrtf(fmaxf(deg[i], 1.0f));
}

// ---------------- edge scatter: accum[dst] += scaled[src] ----------------
// 16 threads per edge, float4 gather + red.global.add.v4.f32 scatter.
__global__ __launch_bounds__(256) void scatter_kernel(
    const int* __restrict__ src, const int* __restrict__ dst,
    const float* __restrict__ scaled, float* __restrict__ accum)
{
    int idx = blockIdx.x * 256 + threadIdx.x;  // exactly Ee*16 threads
    int e = idx >> 4;
    int c = (idx & 15) << 2;
    int s = src[e];
    int d = dst[e];
    float4 v = *(const float4*)(scaled + (size_t)s * 64 + c);
    float* p = accum + (size_t)d * 64 + c;
    asm volatile("red.global.add.v4.f32 [%0], {%1,%2,%3,%4};"
                 :: "l"(p), "f"(v.x), "f"(v.y), "f"(v.z), "f"(v.w)
                 : "memory");
}

// ---------------- fused dual-input GEMM ----------------
// C[n][c] = sum_k A[n][k]*W[k][c]  (+ sum_k (sB*B[n][k])*W[64+k][c] if B)  + bias[c]
// sB = -rowscaleB[n] if rowscaleB else 1.
// Optional: leaky_relu; hall set/add; epilogue prep of (scaled,accum) for next scatter.
__global__ __launch_bounds__(256) void gemm_dual_kernel(
    const float* __restrict__ A, const float* __restrict__ B,
    const float* __restrict__ rowscaleB,
    const float* __restrict__ W, const float* __restrict__ bias,
    float* __restrict__ C,
    float* __restrict__ hall, int hall_mode,          // 0 none, 1 set, 2 add
    int act,
    const float* __restrict__ prep_dinv,
    float* __restrict__ scaled_out, float* __restrict__ accum_out)
{
    __shared__ float Asub[64][68];   // [k][node], 16B-aligned rows (68*4=272=16*17)
    __shared__ float Wsub[64][65];   // [k][col], conflict-free column reads

    const int tid  = threadIdx.x;
    const int base = blockIdx.x * 64;
    const int col  = tid & 63;
    const int ng16 = (tid >> 6) << 4;   // node group start (0,16,32,48)

    unsigned long long acc[8];
#pragma unroll
    for (int j = 0; j < 8; j++) acc[j] = 0ull;

    const int nchunks = B ? 2 : 1;
    for (int ch = 0; ch < nchunks; ch++) {
        const float* srcmat = ch ? B : A;
        // ---- stage A/B (transposed) and W chunk ----
        {
            const int nl = tid >> 4;
            const int c4 = (tid & 15) << 2;
#pragma unroll
            for (int rr = 0; rr < 4; rr++) {
                int row   = nl + rr * 16;
                int gnode = base + row;
                float4 v = make_float4(0.f, 0.f, 0.f, 0.f);
                float s = 1.0f;
                if (gnode < Nn) {
                    v = *(const float4*)(srcmat + (size_t)gnode * 64 + c4);
                    if (ch == 1 && rowscaleB) s = -rowscaleB[gnode];
                }
                v.x *= s; v.y *= s; v.z *= s; v.w *= s;
                Asub[c4 + 0][row] = v.x;
                Asub[c4 + 1][row] = v.y;
                Asub[c4 + 2][row] = v.z;
                Asub[c4 + 3][row] = v.w;

                float4 w = *(const float4*)(W + (size_t)(ch * 64 + row) * 64 + c4);
                Wsub[row][c4 + 0] = w.x;
                Wsub[row][c4 + 1] = w.y;
                Wsub[row][c4 + 2] = w.z;
                Wsub[row][c4 + 3] = w.w;
            }
        }
        __syncthreads();
        // ---- compute: 16 nodes x 1 col per thread, packed f32x2 FMAs ----
#pragma unroll 8
        for (int k = 0; k < 64; k++) {
            float bw = Wsub[k][col];
            unsigned long long b2 = pk2(bw, bw);
            const float4* ap = (const float4*)&Asub[k][ng16];
            float4 a0 = ap[0], a1 = ap[1], a2 = ap[2], a3 = ap[3];
            fma2(acc[0], pk2(a0.x, a0.y), b2);
            fma2(acc[1], pk2(a0.z, a0.w), b2);
            fma2(acc[2], pk2(a1.x, a1.y), b2);
            fma2(acc[3], pk2(a1.z, a1.w), b2);
            fma2(acc[4], pk2(a2.x, a2.y), b2);
            fma2(acc[5], pk2(a2.z, a2.w), b2);
            fma2(acc[6], pk2(a3.x, a3.y), b2);
            fma2(acc[7], pk2(a3.z, a3.w), b2);
        }
        __syncthreads();
    }

    // ---- epilogue ----
    const float bc = bias[col];
#pragma unroll
    for (int j = 0; j < 8; j++) {
        float2 v = upk2(acc[j]);
#pragma unroll
        for (int t = 0; t < 2; t++) {
            int nloc  = ng16 + 2 * j + t;
            int gnode = base + nloc;
            if (gnode >= Nn) continue;
            float val = (t ? v.y : v.x) + bc;
            if (act) val = val > 0.f ? val : 0.01f * val;
            size_t idx = (size_t)gnode * 64 + col;
            C[idx] = val;
            if (hall_mode == 1)      hall[idx] = val;
            else if (hall_mode == 2) hall[idx] += val;
            if (scaled_out) {
                scaled_out[idx] = val * prep_dinv[gnode];
                accum_out[idx]  = 0.f;
            }
        }
    }
}

// ---------------- final: out = leaky_relu(hall) @ W4 + b4  ([N,64]->[N,2]) ----------------
__global__ __launch_bounds__(128) void final_kernel(
    const float* __restrict__ hall, const float* __restrict__ W4,
    const float* __restrict__ b4, float* __restrict__ out)
{
    __shared__ float s[64][65];
    __shared__ float w4[128];
    __shared__ float bb[2];
    const int tid  = threadIdx.x;
    const int base = blockIdx.x * 64;
    w4[tid] = W4[tid];
    if (tid < 2) bb[tid] = b4[tid];
    for (int i = tid; i < 64 * 64; i += 128) {
        int r = i >> 6, c = i & 63;
        int g = base + r;
        s[r][c] = (g < Nn) ? hall[(size_t)g * 64 + c] : 0.f;
    }
    __syncthreads();
    int node = tid >> 1, cc = tid & 1;
    int g = base + node;
    if (g < Nn) {
        float acc = bb[cc];
#pragma unroll
        for (int k = 0; k < 64; k++) {
            float z = s[node][k];
            z = z > 0.f ? z : 0.01f * z;
            acc += z * w4[k * 2 + cc];
        }
        out[(size_t)g * 2 + cc] = acc;
    }
}

// ---------------- launch ----------------
extern "C" void kernel_launch(void* const* d_in, const int* in_sizes, int n_in,
                              void* d_out, int out_size)
{
    const float* x   = (const float*)d_in[0];
    const int*   src = (const int*)d_in[1];
    const int*   dst = (const int*)d_in[2];
    const float* W1  = (const float*)d_in[3];
    const float* b1  = (const float*)d_in[4];
    const float* W2  = (const float*)d_in[5];
    const float* b2  = (const float*)d_in[6];
    const float* Wc1 = (const float*)d_in[7];
    const float* bc1 = (const float*)d_in[8];
    const float* Wc2 = (const float*)d_in[9];
    const float* bc2 = (const float*)d_in[10];
    const float* W3  = (const float*)d_in[11];
    const float* b3  = (const float*)d_in[12];
    const float* W4  = (const float*)d_in[13];
    const float* b4  = (const float*)d_in[14];
    float* out = (float*)d_out;

    void *p;
    float *h, *h0, *h1, *hall, *scal, *acc, *dinv;
    cudaGetSymbolAddress(&p, g_h);    h    = (float*)p;
    cudaGetSymbolAddress(&p, g_h0);   h0   = (float*)p;
    cudaGetSymbolAddress(&p, g_h1);   h1   = (float*)p;
    cudaGetSymbolAddress(&p, g_hall); hall = (float*)p;
    cudaGetSymbolAddress(&p, g_scal); scal = (float*)p;
    cudaGetSymbolAddress(&p, g_acc);  acc  = (float*)p;
    cudaGetSymbolAddress(&p, g_dinv); dinv = (float*)p;

    const int GB = (Nn + 63) / 64;        // 1563 gemm/final blocks
    const int SB = (Ee * 16) / 256;       // 62500 scatter blocks

    // degrees -> dinv (per relation)
    zero_dinv_kernel<<<(Rr * Nn + 255) / 256, 256>>>(dinv);
    count_deg_kernel<<<(Rr * Ee + 255) / 256, 256>>>(dst, dinv);
    fin_dinv_kernel<<<(Rr * Nn + 255) / 256, 256>>>(dinv);

    // h = act(x@W1+b1); h = act(h@W2+b2), fused prep of (scaled, accum) for r=0
    gemm_dual_kernel<<<GB, 256>>>(x,  nullptr, nullptr, W1, b1, h0,
                                  nullptr, 0, 1, nullptr, nullptr, nullptr);
    gemm_dual_kernel<<<GB, 256>>>(h0, nullptr, nullptr, W2, b2, h,
                                  nullptr, 0, 1, dinv, scal, acc);

    for (int r = 0; r < Rr; r++) {
        const float* dv = dinv + (size_t)r * Nn;
        const int*   sr = src + (size_t)r * Ee;
        const int*   dr = dst + (size_t)r * Ee;

        // h0 = cheb(h):  accum = segsum(scaled, dst);  h0 = [h, -dinv*accum]@Wc1 + bc1
        scatter_kernel<<<SB, 256>>>(sr, dr, scal, acc);
        gemm_dual_kernel<<<GB, 256>>>(h, acc, dv, Wc1, bc1, h0,
                                      nullptr, 0, 0, dv, scal, acc);  // prep scaled0, zero accum

        // h1 = cheb(h0)
        scatter_kernel<<<SB, 256>>>(sr, dr, scal, acc);
        gemm_dual_kernel<<<GB, 256>>>(h0, acc, dv, Wc2, bc2, h1,
                                      nullptr, 0, 0, nullptr, nullptr, nullptr);

        // h = [h0,h1]@W3 + b3;  hall (set on r=0, add after);  prep next relation
        const float* ndv = (r + 1 < Rr) ? (dinv + (size_t)(r + 1) * Nn) : nullptr;
        gemm_dual_kernel<<<GB, 256>>>(h0, h1, nullptr, W3, b3, h,
                                      hall, (r == 0) ? 1 : 2, 0,
                                      ndv, ndv ? scal : nullptr, ndv ? acc : nullptr);
    }

    final_kernel<<<GB, 128>>>(hall, W4, b4, out);
}